// round 12
// baseline (speedup 1.0000x reference)
#include <cuda_runtime.h>
#include <cuda_fp16.h>
#include <math.h>
#include <stdint.h>

#define Bq 65536

// ---------------- device workspaces (sanctioned __device__ scratch) --------
__device__ __align__(16) unsigned char g_wb[24u * 131072u];     // 3 MB: BT fp16
__device__ __align__(16) unsigned short g_z[12ull * Bq * 256];  // z vectors fp16

// ---------------- SMEM layout (bytes) ----------------
#define BIAS_OFF 0
#define BST_OFF 68608
#define SCR_OFF 102400
#define SM_BYTES 111104
#define BPART 16896          // 32*528
#define ASTRIDE 528          // bytes per row (264 fp16)

__constant__ int c_A[2] = {1024, 34816};

// ---------------- helpers ----------------
__device__ __forceinline__ uint32_t smem_u32(const void* p) {
    uint32_t a;
    asm("{ .reg .u64 t; cvta.to.shared.u64 t, %1; cvt.u32.u64 %0, t; }" : "=r"(a) : "l"(p));
    return a;
}

#define LDSM4(r, addr) \
    asm volatile("ldmatrix.sync.aligned.m8n8.x4.shared.b16 {%0,%1,%2,%3}, [%4];" \
        : "=r"((r)[0]), "=r"((r)[1]), "=r"((r)[2]), "=r"((r)[3]) : "r"(addr))

#define MMA(acc, a, bb0, bb1) \
    asm volatile("mma.sync.aligned.m16n8k16.row.col.f32.f16.f16.f32 " \
        "{%0,%1,%2,%3},{%4,%5,%6,%7},{%8,%9},{%0,%1,%2,%3};" \
        : "+f"((acc)[0]), "+f"((acc)[1]), "+f"((acc)[2]), "+f"((acc)[3]) \
        : "r"((a)[0]), "r"((a)[1]), "r"((a)[2]), "r"((a)[3]), "r"(bb0), "r"(bb1))

__device__ __forceinline__ void cpa16(uint32_t dst, const void* src) {
    asm volatile("cp.async.cg.shared.global [%0], [%1], 16;" :: "r"(dst), "l"(src));
}
#define CP_COMMIT() asm volatile("cp.async.commit_group;" ::: "memory")
#define CP_WAIT0()  asm volatile("cp.async.wait_group 0;" ::: "memory")

__device__ __forceinline__ uint32_t pack_h2(float a, float b) {
    __half2 h = __floats2half2_rn(a, b);
    return *(uint32_t*)&h;
}

__device__ __forceinline__ float gelu_f(float v) {
    return 0.5f * v * (1.0f + erff(v * 0.70710678118654752f));
}

// ---------------- prep: weights -> BT fp16 blobs ----------------
__global__ void prep_kernel(const float* __restrict__ Tw1, const float* __restrict__ Tw2,
                            const float* __restrict__ Ew1, const float* __restrict__ Ew2) {
    int mat = blockIdx.x >> 3, sub = blockIdx.x & 7;
    const float* src = (mat < 11) ? Tw1 + (size_t)mat * 65536
                     : (mat < 22) ? Tw2 + (size_t)(mat - 11) * 65536
                     : (mat == 22) ? Ew1 : Ew2;
    unsigned char* baseH = g_wb + (size_t)mat * 131072u;
    for (int i = 0; i < 32; ++i) {
        int idx = sub * 8192 + i * 256 + threadIdx.x;
        int k = idx >> 8, n = idx & 255;
        __half h = __float2half_rn(src[idx]);
        *(unsigned short*)(baseH + (size_t)n * 512 + (size_t)k * 2) = *(unsigned short*)&h;
    }
}

// ---------------- main fused MLP kernel ----------------
extern __shared__ unsigned char smem[];

__device__ __forceinline__ void issueB(uint32_t sb, int tid, int mat, int c, int stage) {
    const unsigned char* srcbase = g_wb + (size_t)mat * 131072u;
    uint32_t dstbase = sb + BST_OFF + stage * BPART;
#pragma unroll
    for (int i = 0; i < 4; ++i) {
        int g = tid + 256 * i;           // 0..1023
        int rw = g >> 5;                 // row within chunk 0..31
        int u = g & 31;                  // 16B unit within 512B row
        uint32_t dst = dstbase + rw * ASTRIDE + u * 16;
        const unsigned char* s = srcbase + (size_t)(c * 32 + rw) * 512 + (size_t)u * 16;
        cpa16(dst, s);
    }
    CP_COMMIT();
}

__device__ __forceinline__ void do_layer(
    uint32_t sb, int tid, int cur, int mat, int nextMat,
    const float* __restrict__ biasPtr, bool do_gelu, bool toA,
    int slot, int b0)
{
    float* bias_s = (float*)(smem + BIAS_OFF);
    bias_s[tid] = biasPtr[tid];

    const int w = tid >> 5, lane = tid & 31;
    const int kh = w >> 2;              // K half (0: k<128, 1: k>=128)
    const int wm = (w >> 1) & 1;        // 32-row slice
    const int wn = w & 1;               // 16-col slice
    const int gid = lane >> 2, tig = lane & 3;

    const int rowA0 = wm * 32 + (lane & 15);
    const int koffA = (lane >> 4) * 16 + kh * 256;     // bytes
    const int rowB = wn * 16 + ((lane >> 4) << 3) + (lane & 7);
    const int koffB = ((lane >> 3) & 1) * 16 + kh * 256;

    const uint32_t aB = sb + c_A[cur] + rowA0 * ASTRIDE + koffA;
    float* scr = (float*)(smem + SCR_OFF);

    // ---- A-stationary: preload this warp's A slice (32 rows x 128 k fp16) ----
    uint32_t areg[2][8][4];
#pragma unroll
    for (int t = 0; t < 2; ++t)
#pragma unroll
    for (int ks = 0; ks < 8; ++ks)
        LDSM4(areg[t][ks], aB + t * 16 * ASTRIDE + ks * 32);

#pragma unroll 1
    for (int c = 0; c < 8; ++c) {
        CP_WAIT0();
        __syncthreads();
        if (c + 1 < 8) issueB(sb, tid, mat, c + 1, (c + 1) & 1);
        else if (nextMat >= 0) issueB(sb, tid, nextMat, 0, 0);

        uint32_t bB = sb + BST_OFF + (c & 1) * BPART + rowB * ASTRIDE + koffB;

        float acc[2][2][4] = {};

#pragma unroll
        for (int ks = 0; ks < 8; ++ks) {
            uint32_t bh[4];
            LDSM4(bh, bB);
            bB += 32;
            MMA(acc[0][0], areg[0][ks], bh[0], bh[1]); MMA(acc[0][1], areg[0][ks], bh[2], bh[3]);
            MMA(acc[1][0], areg[1][ks], bh[0], bh[1]); MMA(acc[1][1], areg[1][ks], bh[2], bh[3]);
        }

        // ---- balanced cross-K exchange: write NON-owned subtile (t = 1-kh) ----
        const int tw = 1 - kh;
        const int rw0 = wm * 32 + tw * 16 + gid;
        const int cb = wn * 16 + 2 * tig;
#pragma unroll
        for (int u = 0; u < 2; ++u) {
            int cc = cb + u * 8;
            *(float2*)&scr[rw0 * 34 + cc]       = make_float2(acc[tw][u][0], acc[tw][u][1]);
            *(float2*)&scr[(rw0 + 8) * 34 + cc] = make_float2(acc[tw][u][2], acc[tw][u][3]);
        }
        __syncthreads();

        // ---- epilogue for OWNED subtile (t = kh), all 8 warps ----
        const int ro = wm * 32 + kh * 16 + gid;
#pragma unroll
        for (int u = 0; u < 2; ++u) {
            int cc = cb + u * 8;
            int gcol = c * 32 + cc;
            float2 p0 = *(float2*)&scr[ro * 34 + cc];
            float2 p1 = *(float2*)&scr[(ro + 8) * 34 + cc];
            float v00 = acc[kh][u][0] + p0.x + bias_s[gcol];
            float v01 = acc[kh][u][1] + p0.y + bias_s[gcol + 1];
            float v10 = acc[kh][u][2] + p1.x + bias_s[gcol];
            float v11 = acc[kh][u][3] + p1.y + bias_s[gcol + 1];
            if (do_gelu) {
                v00 = gelu_f(v00); v01 = gelu_f(v01);
                v10 = gelu_f(v10); v11 = gelu_f(v11);
            }
            if (toA) {
                unsigned char* da = smem + c_A[cur ^ 1];
                *(uint32_t*)(da + ro * ASTRIDE + gcol * 2)       = pack_h2(v00, v01);
                *(uint32_t*)(da + (ro + 8) * ASTRIDE + gcol * 2) = pack_h2(v10, v11);
            } else {
                unsigned short* zb = g_z + ((size_t)slot * Bq + b0) * 256;
                *(uint32_t*)(zb + (size_t)ro * 256 + gcol)       = pack_h2(v00, v01);
                *(uint32_t*)(zb + (size_t)(ro + 8) * 256 + gcol) = pack_h2(v10, v11);
            }
        }
    }
    __syncthreads();
}

__global__ void __launch_bounds__(256, 2)
mlp_kernel(const float* __restrict__ x,
           const float* __restrict__ Tb1, const float* __restrict__ Tb2,
           const float* __restrict__ Eb1, const float* __restrict__ Eb2)
{
    const uint32_t sb = smem_u32(smem);
    const int tid = threadIdx.x;
    const int b0 = blockIdx.x * 64;

    issueB(sb, tid, 0, 0, 0);   // prefetch chunk0 of first layer

#pragma unroll 1
    for (int br = 0; br < 12; ++br) {
        // load x rows -> A0 (fp16)
        {
            const int row = tid >> 2;
            const int cbase = (tid & 3) * 64;
            const float4* src = (const float4*)(x + (size_t)(b0 + row) * 256 + cbase);
            unsigned char* da = smem + c_A[0] + row * ASTRIDE;
#pragma unroll
            for (int i = 0; i < 16; ++i) {
                float4 v = src[i];
                int col = cbase + i * 4;
                *(uint32_t*)(da + col * 2)     = pack_h2(v.x, v.y);
                *(uint32_t*)(da + col * 2 + 4) = pack_h2(v.z, v.w);
            }
        }
        __syncthreads();

        int cur = 0;
        if (br < 11) {
            do_layer(sb, tid, cur, br,      11 + br, Tb1 + br * 256, true,  true, 0, b0); cur ^= 1;
            do_layer(sb, tid, cur, 11 + br, 22,      Tb2 + br * 256, false, true, 0, b0); cur ^= 1;
            do_layer(sb, tid, cur, 22,      23,      Eb1, true,  true,  0,  b0); cur ^= 1;
            do_layer(sb, tid, cur, 23, (br + 1 < 11) ? br + 1 : 22, Eb2, false, false, br, b0);
        } else {
            do_layer(sb, tid, cur, 22, 23, Eb1, true,  true,  0,  b0); cur ^= 1;
            do_layer(sb, tid, cur, 23, -1, Eb2, false, false, br, b0);
        }
    }
}

// ---------------- scoring kernel: warp per row ----------------
__global__ void __launch_bounds__(256)
score_kernel(float* __restrict__ out) {
    int lane = threadIdx.x & 31;
    int wid = blockIdx.x * (blockDim.x >> 5) + (threadIdx.x >> 5);
    int nw = gridDim.x * (blockDim.x >> 5);
    for (int row = wid; row < Bq; row += nw) {
        float v[12][8];
#pragma unroll
        for (int s = 0; s < 12; ++s) {
            const __half2* p = (const __half2*)g_z + ((size_t)s * Bq + row) * 128 + lane;
#pragma unroll
            for (int u = 0; u < 4; ++u) {
                float2 t = __half22float2(p[u * 32]);
                v[s][2 * u] = t.x; v[s][2 * u + 1] = t.y;
            }
        }
        float inrm[12];
#pragma unroll
        for (int s = 0; s < 12; ++s) {
            float d = 0.f;
#pragma unroll
            for (int u = 0; u < 8; ++u) d = fmaf(v[s][u], v[s][u], d);
#pragma unroll
            for (int o = 16; o; o >>= 1) d += __shfl_xor_sync(0xffffffffu, d, o);
            inrm[s] = sqrtf(d);
        }
        float negs[11];
#pragma unroll
        for (int k = 0; k < 11; ++k) negs[k] = 0.f;
#pragma unroll
        for (int l = 0; l < 11; ++l) {
#pragma unroll
            for (int k = l + 1; k < 11; ++k) {
                float d = 0.f;
#pragma unroll
                for (int u = 0; u < 8; ++u) d = fmaf(v[l][u], v[k][u], d);
#pragma unroll
                for (int o = 16; o; o >>= 1) d += __shfl_xor_sync(0xffffffffu, d, o);
                float e = expf(d / fmaxf(inrm[l] * inrm[k], 1e-8f));
                negs[l] += e; negs[k] += e;
            }
        }
        float tot = 0.f;
#pragma unroll
        for (int k = 0; k < 11; ++k) {
            float d = 0.f;
#pragma unroll
            for (int u = 0; u < 8; ++u) d = fmaf(v[11][u], v[k][u], d);
#pragma unroll
            for (int o = 16; o; o >>= 1) d += __shfl_xor_sync(0xffffffffu, d, o);
            float sim = expf(d / fmaxf(inrm[11] * inrm[k], 1e-8f));
            tot += log1pf(negs[k] / sim);
        }
        if (lane == 0) out[row] = tot;
    }
}

// ---------------- launcher ----------------
extern "C" void kernel_launch(void* const* d_in, const int* in_sizes, int n_in,
                              void* d_out, int out_size) {
    const float* x   = (const float*)d_in[0];
    const float* Tw1 = (const float*)d_in[1];
    const float* Tb1 = (const float*)d_in[2];
    const float* Tw2 = (const float*)d_in[3];
    const float* Tb2 = (const float*)d_in[4];
    const float* Ew1 = (const float*)d_in[5];
    const float* Eb1 = (const float*)d_in[6];
    const float* Ew2 = (const float*)d_in[7];
    const float* Eb2 = (const float*)d_in[8];
    float* out = (float*)d_out;

    cudaFuncSetAttribute(mlp_kernel, cudaFuncAttributeMaxDynamicSharedMemorySize, SM_BYTES);

    prep_kernel<<<192, 256>>>(Tw1, Tw2, Ew1, Ew2);
    mlp_kernel<<<Bq / 64, 256, SM_BYTES>>>(x, Tb1, Tb2, Eb1, Eb2);
    score_kernel<<<1024, 256>>>(out);
}

// round 13
// speedup vs baseline: 1.0748x; 1.0748x over previous
#include <cuda_runtime.h>
#include <cuda_fp16.h>
#include <math.h>
#include <stdint.h>

#define Bq 65536

// ---------------- device workspaces (sanctioned __device__ scratch) --------
__device__ __align__(16) unsigned char g_wb[24u * 131072u];     // 3 MB: BT fp16
__device__ __align__(16) unsigned short g_z[12ull * Bq * 256];  // z vectors fp16

// ---------------- SMEM layout (bytes) ----------------
#define BIAS_OFF 0
#define BST_OFF 68608
#define SCR_OFF 102400
#define SM_BYTES 111104
#define BPART 16896          // 32*528
#define ASTRIDE 528          // bytes per row (264 fp16)

__constant__ int c_A[2] = {1024, 34816};

// ---------------- helpers ----------------
__device__ __forceinline__ uint32_t smem_u32(const void* p) {
    uint32_t a;
    asm("{ .reg .u64 t; cvta.to.shared.u64 t, %1; cvt.u32.u64 %0, t; }" : "=r"(a) : "l"(p));
    return a;
}

#define LDSM4(r, addr) \
    asm volatile("ldmatrix.sync.aligned.m8n8.x4.shared.b16 {%0,%1,%2,%3}, [%4];" \
        : "=r"((r)[0]), "=r"((r)[1]), "=r"((r)[2]), "=r"((r)[3]) : "r"(addr))

#define MMA(acc, a, bb0, bb1) \
    asm volatile("mma.sync.aligned.m16n8k16.row.col.f32.f16.f16.f32 " \
        "{%0,%1,%2,%3},{%4,%5,%6,%7},{%8,%9},{%0,%1,%2,%3};" \
        : "+f"((acc)[0]), "+f"((acc)[1]), "+f"((acc)[2]), "+f"((acc)[3]) \
        : "r"((a)[0]), "r"((a)[1]), "r"((a)[2]), "r"((a)[3]), "r"(bb0), "r"(bb1))

__device__ __forceinline__ void cpa16(uint32_t dst, const void* src) {
    asm volatile("cp.async.cg.shared.global [%0], [%1], 16;" :: "r"(dst), "l"(src));
}
#define CP_COMMIT() asm volatile("cp.async.commit_group;" ::: "memory")
#define CP_WAIT0()  asm volatile("cp.async.wait_group 0;" ::: "memory")

__device__ __forceinline__ uint32_t pack_h2(float a, float b) {
    __half2 h = __floats2half2_rn(a, b);
    return *(uint32_t*)&h;
}

__device__ __forceinline__ float gelu_f(float v) {
    return 0.5f * v * (1.0f + erff(v * 0.70710678118654752f));
}

// ---------------- prep: weights -> BT fp16 blobs ----------------
__global__ void prep_kernel(const float* __restrict__ Tw1, const float* __restrict__ Tw2,
                            const float* __restrict__ Ew1, const float* __restrict__ Ew2) {
    int mat = blockIdx.x >> 3, sub = blockIdx.x & 7;
    const float* src = (mat < 11) ? Tw1 + (size_t)mat * 65536
                     : (mat < 22) ? Tw2 + (size_t)(mat - 11) * 65536
                     : (mat == 22) ? Ew1 : Ew2;
    unsigned char* baseH = g_wb + (size_t)mat * 131072u;
    for (int i = 0; i < 32; ++i) {
        int idx = sub * 8192 + i * 256 + threadIdx.x;
        int k = idx >> 8, n = idx & 255;
        __half h = __float2half_rn(src[idx]);
        *(unsigned short*)(baseH + (size_t)n * 512 + (size_t)k * 2) = *(unsigned short*)&h;
    }
}

// ---------------- main fused MLP kernel ----------------
extern __shared__ unsigned char smem[];

__device__ __forceinline__ void issueB(uint32_t sb, int tid, int mat, int c, int stage) {
    const unsigned char* srcbase = g_wb + (size_t)mat * 131072u;
    uint32_t dstbase = sb + BST_OFF + stage * BPART;
#pragma unroll
    for (int i = 0; i < 4; ++i) {
        int g = tid + 256 * i;           // 0..1023
        int rw = g >> 5;                 // row within chunk 0..31
        int u = g & 31;                  // 16B unit within 512B row
        uint32_t dst = dstbase + rw * ASTRIDE + u * 16;
        const unsigned char* s = srcbase + (size_t)(c * 32 + rw) * 512 + (size_t)u * 16;
        cpa16(dst, s);
    }
    CP_COMMIT();
}

__device__ __forceinline__ void do_layer(
    uint32_t sb, int tid, int cur, int mat, int nextMat,
    const float* __restrict__ biasPtr, bool do_gelu, bool toA,
    int slot, int b0)
{
    float* bias_s = (float*)(smem + BIAS_OFF);
    bias_s[tid] = biasPtr[tid];

    const int w = tid >> 5, lane = tid & 31;
    const int kh = w >> 2;              // K half (0: k<128, 1: k>=128)
    const int wm = (w >> 1) & 1;        // 32-row slice
    const int wn = w & 1;               // 16-col slice
    const int gid = lane >> 2, tig = lane & 3;

    const int rowA0 = wm * 32 + (lane & 15);
    const int koffA = (lane >> 4) * 16 + kh * 256;     // bytes
    const int rowB = wn * 16 + ((lane >> 4) << 3) + (lane & 7);
    const int koffB = ((lane >> 3) & 1) * 16 + kh * 256;

    const uint32_t aB = sb + c_A[cur] + rowA0 * ASTRIDE + koffA;
    float* scr = (float*)(smem + SCR_OFF);

    // ---- A-stationary: preload this warp's A slice (32 rows x 128 k fp16) ----
    uint32_t areg[2][8][4];
#pragma unroll
    for (int t = 0; t < 2; ++t)
#pragma unroll
    for (int ks = 0; ks < 8; ++ks)
        LDSM4(areg[t][ks], aB + t * 16 * ASTRIDE + ks * 32);

#pragma unroll 1
    for (int c = 0; c < 8; ++c) {
        CP_WAIT0();
        __syncthreads();
        if (c + 1 < 8) issueB(sb, tid, mat, c + 1, (c + 1) & 1);
        else if (nextMat >= 0) issueB(sb, tid, nextMat, 0, 0);

        uint32_t bB = sb + BST_OFF + (c & 1) * BPART + rowB * ASTRIDE + koffB;

        float acc[2][2][4] = {};

#pragma unroll
        for (int ks = 0; ks < 8; ++ks) {
            uint32_t bh[4];
            LDSM4(bh, bB);
            bB += 32;
            MMA(acc[0][0], areg[0][ks], bh[0], bh[1]); MMA(acc[0][1], areg[0][ks], bh[2], bh[3]);
            MMA(acc[1][0], areg[1][ks], bh[0], bh[1]); MMA(acc[1][1], areg[1][ks], bh[2], bh[3]);
        }

        const int rbase = wm * 32 + gid;
        const int cb = wn * 16 + 2 * tig;
        if (kh) {
#pragma unroll
            for (int t = 0; t < 2; ++t)
#pragma unroll
            for (int u = 0; u < 2; ++u) {
                int r = rbase + t * 16, cc = cb + u * 8;
                *(float2*)&scr[r * 34 + cc]       = make_float2(acc[t][u][0], acc[t][u][1]);
                *(float2*)&scr[(r + 8) * 34 + cc] = make_float2(acc[t][u][2], acc[t][u][3]);
            }
        }
        __syncthreads();
        if (!kh) {
#pragma unroll
            for (int t = 0; t < 2; ++t)
#pragma unroll
            for (int u = 0; u < 2; ++u) {
                int r = rbase + t * 16, cc = cb + u * 8;
                int gcol = c * 32 + cc;
                float2 p0 = *(float2*)&scr[r * 34 + cc];
                float2 p1 = *(float2*)&scr[(r + 8) * 34 + cc];
                float v00 = acc[t][u][0] + p0.x + bias_s[gcol];
                float v01 = acc[t][u][1] + p0.y + bias_s[gcol + 1];
                float v10 = acc[t][u][2] + p1.x + bias_s[gcol];
                float v11 = acc[t][u][3] + p1.y + bias_s[gcol + 1];
                if (do_gelu) {
                    v00 = gelu_f(v00); v01 = gelu_f(v01);
                    v10 = gelu_f(v10); v11 = gelu_f(v11);
                }
                if (toA) {
                    unsigned char* da = smem + c_A[cur ^ 1];
                    *(uint32_t*)(da + r * ASTRIDE + gcol * 2)       = pack_h2(v00, v01);
                    *(uint32_t*)(da + (r + 8) * ASTRIDE + gcol * 2) = pack_h2(v10, v11);
                } else {
                    unsigned short* zb = g_z + ((size_t)slot * Bq + b0) * 256;
                    *(uint32_t*)(zb + (size_t)r * 256 + gcol)       = pack_h2(v00, v01);
                    *(uint32_t*)(zb + (size_t)(r + 8) * 256 + gcol) = pack_h2(v10, v11);
                }
            }
        }
    }
    __syncthreads();
}

__global__ void __launch_bounds__(256, 2)
mlp_kernel(const float* __restrict__ x,
           const float* __restrict__ Tb1, const float* __restrict__ Tb2,
           const float* __restrict__ Eb1, const float* __restrict__ Eb2)
{
    const uint32_t sb = smem_u32(smem);
    const int tid = threadIdx.x;
    const int b0 = blockIdx.x * 64;

    issueB(sb, tid, 0, 0, 0);   // prefetch chunk0 of first layer

#pragma unroll 1
    for (int br = 0; br < 12; ++br) {
        // load x rows -> A0 (fp16)
        {
            const int row = tid >> 2;
            const int cbase = (tid & 3) * 64;
            const float4* src = (const float4*)(x + (size_t)(b0 + row) * 256 + cbase);
            unsigned char* da = smem + c_A[0] + row * ASTRIDE;
#pragma unroll
            for (int i = 0; i < 16; ++i) {
                float4 v = src[i];
                int col = cbase + i * 4;
                *(uint32_t*)(da + col * 2)     = pack_h2(v.x, v.y);
                *(uint32_t*)(da + col * 2 + 4) = pack_h2(v.z, v.w);
            }
        }
        __syncthreads();

        int cur = 0;
        if (br < 11) {
            do_layer(sb, tid, cur, br,      11 + br, Tb1 + br * 256, true,  true, 0, b0); cur ^= 1;
            do_layer(sb, tid, cur, 11 + br, 22,      Tb2 + br * 256, false, true, 0, b0); cur ^= 1;
            do_layer(sb, tid, cur, 22,      23,      Eb1, true,  true,  0,  b0); cur ^= 1;
            do_layer(sb, tid, cur, 23, (br + 1 < 11) ? br + 1 : 22, Eb2, false, false, br, b0);
        } else {
            do_layer(sb, tid, cur, 22, 23, Eb1, true,  true,  0,  b0); cur ^= 1;
            do_layer(sb, tid, cur, 23, -1, Eb2, false, false, br, b0);
        }
    }
}

// ---------------- scoring kernel: warp per row ----------------
__global__ void __launch_bounds__(256)
score_kernel(float* __restrict__ out) {
    int lane = threadIdx.x & 31;
    int wid = blockIdx.x * (blockDim.x >> 5) + (threadIdx.x >> 5);
    int nw = gridDim.x * (blockDim.x >> 5);
    for (int row = wid; row < Bq; row += nw) {
        float v[12][8];
#pragma unroll
        for (int s = 0; s < 12; ++s) {
            const __half2* p = (const __half2*)g_z + ((size_t)s * Bq + row) * 128 + lane;
#pragma unroll
            for (int u = 0; u < 4; ++u) {
                float2 t = __half22float2(p[u * 32]);
                v[s][2 * u] = t.x; v[s][2 * u + 1] = t.y;
            }
        }
        float inrm[12];
#pragma unroll
        for (int s = 0; s < 12; ++s) {
            float d = 0.f;
#pragma unroll
            for (int u = 0; u < 8; ++u) d = fmaf(v[s][u], v[s][u], d);
#pragma unroll
            for (int o = 16; o; o >>= 1) d += __shfl_xor_sync(0xffffffffu, d, o);
            inrm[s] = sqrtf(d);
        }
        float negs[11];
#pragma unroll
        for (int k = 0; k < 11; ++k) negs[k] = 0.f;
#pragma unroll
        for (int l = 0; l < 11; ++l) {
#pragma unroll
            for (int k = l + 1; k < 11; ++k) {
                float d = 0.f;
#pragma unroll
                for (int u = 0; u < 8; ++u) d = fmaf(v[l][u], v[k][u], d);
#pragma unroll
                for (int o = 16; o; o >>= 1) d += __shfl_xor_sync(0xffffffffu, d, o);
                float e = expf(d / fmaxf(inrm[l] * inrm[k], 1e-8f));
                negs[l] += e; negs[k] += e;
            }
        }
        float tot = 0.f;
#pragma unroll
        for (int k = 0; k < 11; ++k) {
            float d = 0.f;
#pragma unroll
            for (int u = 0; u < 8; ++u) d = fmaf(v[11][u], v[k][u], d);
#pragma unroll
            for (int o = 16; o; o >>= 1) d += __shfl_xor_sync(0xffffffffu, d, o);
            float sim = expf(d / fmaxf(inrm[11] * inrm[k], 1e-8f));
            tot += log1pf(negs[k] / sim);
        }
        if (lane == 0) out[row] = tot;
    }
}

// ---------------- launcher ----------------
extern "C" void kernel_launch(void* const* d_in, const int* in_sizes, int n_in,
                              void* d_out, int out_size) {
    const float* x   = (const float*)d_in[0];
    const float* Tw1 = (const float*)d_in[1];
    const float* Tb1 = (const float*)d_in[2];
    const float* Tw2 = (const float*)d_in[3];
    const float* Tb2 = (const float*)d_in[4];
    const float* Ew1 = (const float*)d_in[5];
    const float* Eb1 = (const float*)d_in[6];
    const float* Ew2 = (const float*)d_in[7];
    const float* Eb2 = (const float*)d_in[8];
    float* out = (float*)d_out;

    cudaFuncSetAttribute(mlp_kernel, cudaFuncAttributeMaxDynamicSharedMemorySize, SM_BYTES);

    prep_kernel<<<192, 256>>>(Tw1, Tw2, Ew1, Ew2);
    mlp_kernel<<<Bq / 64, 256, SM_BYTES>>>(x, Tb1, Tb2, Eb1, Eb2);
    score_kernel<<<1024, 256>>>(out);
}

// round 14
// speedup vs baseline: 1.3308x; 1.2381x over previous
#include <cuda_runtime.h>
#include <cuda_fp16.h>
#include <math.h>
#include <stdint.h>

#define Bq 65536

// ---------------- device workspaces (sanctioned __device__ scratch) --------
__device__ __align__(16) unsigned char g_wb[24u * 131072u];     // 3 MB: BT fp16
__device__ __align__(16) unsigned short g_z[12ull * Bq * 256];  // z vectors fp16

// ---------------- SMEM layout (bytes) ----------------
// bias f32[256] @0 ; A @1024 (33792, single buffer) ; B stages @34816 (2 x 16896)
#define BIAS_OFF 0
#define A_OFF 1024
#define BST_OFF 34816
#define SM_BYTES 68608
#define BPART 16896          // 32*528
#define ASTRIDE 528          // bytes per row (264 fp16)

// ---------------- helpers ----------------
__device__ __forceinline__ uint32_t smem_u32(const void* p) {
    uint32_t a;
    asm("{ .reg .u64 t; cvta.to.shared.u64 t, %1; cvt.u32.u64 %0, t; }" : "=r"(a) : "l"(p));
    return a;
}

#define LDSM4(r, addr) \
    asm volatile("ldmatrix.sync.aligned.m8n8.x4.shared.b16 {%0,%1,%2,%3}, [%4];" \
        : "=r"((r)[0]), "=r"((r)[1]), "=r"((r)[2]), "=r"((r)[3]) : "r"(addr))

#define MMA(acc, a, bb0, bb1) \
    asm volatile("mma.sync.aligned.m16n8k16.row.col.f32.f16.f16.f32 " \
        "{%0,%1,%2,%3},{%4,%5,%6,%7},{%8,%9},{%0,%1,%2,%3};" \
        : "+f"((acc)[0]), "+f"((acc)[1]), "+f"((acc)[2]), "+f"((acc)[3]) \
        : "r"((a)[0]), "r"((a)[1]), "r"((a)[2]), "r"((a)[3]), "r"(bb0), "r"(bb1))

__device__ __forceinline__ void cpa16(uint32_t dst, const void* src) {
    asm volatile("cp.async.cg.shared.global [%0], [%1], 16;" :: "r"(dst), "l"(src));
}
#define CP_COMMIT() asm volatile("cp.async.commit_group;" ::: "memory")
#define CP_WAIT0()  asm volatile("cp.async.wait_group 0;" ::: "memory")

__device__ __forceinline__ uint32_t pack_h2(float a, float b) {
    __half2 h = __floats2half2_rn(a, b);
    return *(uint32_t*)&h;
}

__device__ __forceinline__ float gelu_f(float v) {
    return 0.5f * v * (1.0f + erff(v * 0.70710678118654752f));
}

// ---------------- prep: weights -> BT fp16 blobs ----------------
__global__ void prep_kernel(const float* __restrict__ Tw1, const float* __restrict__ Tw2,
                            const float* __restrict__ Ew1, const float* __restrict__ Ew2) {
    int mat = blockIdx.x >> 3, sub = blockIdx.x & 7;
    const float* src = (mat < 11) ? Tw1 + (size_t)mat * 65536
                     : (mat < 22) ? Tw2 + (size_t)(mat - 11) * 65536
                     : (mat == 22) ? Ew1 : Ew2;
    unsigned char* baseH = g_wb + (size_t)mat * 131072u;
    for (int i = 0; i < 32; ++i) {
        int idx = sub * 8192 + i * 256 + threadIdx.x;
        int k = idx >> 8, n = idx & 255;
        __half h = __float2half_rn(src[idx]);
        *(unsigned short*)(baseH + (size_t)n * 512 + (size_t)k * 2) = *(unsigned short*)&h;
    }
}

// ---------------- main fused MLP kernel ----------------
extern __shared__ unsigned char smem[];

__device__ __forceinline__ void issueB(uint32_t sb, int tid, int mat, int c, int stage) {
    const unsigned char* srcbase = g_wb + (size_t)mat * 131072u;
    uint32_t dstbase = sb + BST_OFF + stage * BPART;
#pragma unroll
    for (int i = 0; i < 4; ++i) {
        int g = tid + 256 * i;           // 0..1023
        int rw = g >> 5;                 // row within chunk 0..31
        int u = g & 31;                  // 16B unit within 512B row
        uint32_t dst = dstbase + rw * ASTRIDE + u * 16;
        const unsigned char* s = srcbase + (size_t)(c * 32 + rw) * 512 + (size_t)u * 16;
        cpa16(dst, s);
    }
    CP_COMMIT();
}

__device__ __forceinline__ void do_layer(
    uint32_t sb, int tid, int mat, int nextMat,
    const float* __restrict__ biasPtr, bool do_gelu, bool toA,
    int slot, int b0)
{
    float* bias_s = (float*)(smem + BIAS_OFF);
    bias_s[tid] = biasPtr[tid];

    const int w = tid >> 5, lane = tid & 31;
    const int wm = w >> 1;              // 0..3, 16-row slice
    const int wn = w & 1;               // 16-col slice
    const int gid = lane >> 2, tig = lane & 3;

    const int rowA = wm * 16 + (lane & 15);
    const int koffA = (lane >> 4) * 16;                      // bytes
    const int rowB = wn * 16 + ((lane >> 4) << 3) + (lane & 7);
    const int koffB = ((lane >> 3) & 1) * 16;

    // ---- A-stationary: preload warp's A slice (16 rows x 256 k fp16 = 64 regs) ----
    const uint32_t aB = sb + A_OFF + rowA * ASTRIDE + koffA;
    uint32_t areg[16][4];
#pragma unroll
    for (int ks = 0; ks < 16; ++ks)
        LDSM4(areg[ks], aB + ks * 32);

#pragma unroll 1
    for (int c = 0; c < 8; ++c) {
        CP_WAIT0();
        __syncthreads();
        if (c + 1 < 8) issueB(sb, tid, mat, c + 1, (c + 1) & 1);
        else if (nextMat >= 0) issueB(sb, tid, nextMat, 0, 0);

        uint32_t bB = sb + BST_OFF + (c & 1) * BPART + rowB * ASTRIDE + koffB;

        float acc0[4] = {0.f, 0.f, 0.f, 0.f};
        float acc1[4] = {0.f, 0.f, 0.f, 0.f};

#pragma unroll
        for (int ks = 0; ks < 16; ++ks) {
            uint32_t bh[4];
            LDSM4(bh, bB);
            bB += 32;
            MMA(acc0, areg[ks], bh[0], bh[1]);
            MMA(acc1, areg[ks], bh[2], bh[3]);
        }

        // epilogue: warp owns 16 rows x 16 cols of this chunk; no scratch, no 2nd sync
        const int r0 = wm * 16 + gid;
#pragma unroll
        for (int t = 0; t < 2; ++t) {
            float* ac = t ? acc1 : acc0;
            const int gcol = c * 32 + wn * 16 + t * 8 + 2 * tig;
            float v00 = ac[0] + bias_s[gcol];
            float v01 = ac[1] + bias_s[gcol + 1];
            float v10 = ac[2] + bias_s[gcol];
            float v11 = ac[3] + bias_s[gcol + 1];
            if (do_gelu) {
                v00 = gelu_f(v00); v01 = gelu_f(v01);
                v10 = gelu_f(v10); v11 = gelu_f(v11);
            }
            if (toA) {
                unsigned char* da = smem + A_OFF;
                *(uint32_t*)(da + r0 * ASTRIDE + gcol * 2)       = pack_h2(v00, v01);
                *(uint32_t*)(da + (r0 + 8) * ASTRIDE + gcol * 2) = pack_h2(v10, v11);
            } else {
                unsigned short* zb = g_z + ((size_t)slot * Bq + b0) * 256;
                *(uint32_t*)(zb + (size_t)r0 * 256 + gcol)       = pack_h2(v00, v01);
                *(uint32_t*)(zb + (size_t)(r0 + 8) * 256 + gcol) = pack_h2(v10, v11);
            }
        }
    }
    __syncthreads();
}

__global__ void __launch_bounds__(256, 2)
mlp_kernel(const float* __restrict__ x,
           const float* __restrict__ Tb1, const float* __restrict__ Tb2,
           const float* __restrict__ Eb1, const float* __restrict__ Eb2)
{
    const uint32_t sb = smem_u32(smem);
    const int tid = threadIdx.x;
    const int b0 = blockIdx.x * 64;

    issueB(sb, tid, 0, 0, 0);   // prefetch chunk0 of first layer

#pragma unroll 1
    for (int br = 0; br < 12; ++br) {
        // load x rows -> A (fp16)
        {
            const int row = tid >> 2;
            const int cbase = (tid & 3) * 64;
            const float4* src = (const float4*)(x + (size_t)(b0 + row) * 256 + cbase);
            unsigned char* da = smem + A_OFF + row * ASTRIDE;
#pragma unroll
            for (int i = 0; i < 16; ++i) {
                float4 v = src[i];
                int col = cbase + i * 4;
                *(uint32_t*)(da + col * 2)     = pack_h2(v.x, v.y);
                *(uint32_t*)(da + col * 2 + 4) = pack_h2(v.z, v.w);
            }
        }
        __syncthreads();

        if (br < 11) {
            do_layer(sb, tid, br,      11 + br, Tb1 + br * 256, true,  true, 0, b0);
            do_layer(sb, tid, 11 + br, 22,      Tb2 + br * 256, false, true, 0, b0);
            do_layer(sb, tid, 22,      23,      Eb1, true,  true,  0,  b0);
            do_layer(sb, tid, 23, (br + 1 < 11) ? br + 1 : 22, Eb2, false, false, br, b0);
        } else {
            do_layer(sb, tid, 22, 23, Eb1, true,  true,  0,  b0);
            do_layer(sb, tid, 23, -1, Eb2, false, false, br, b0);
        }
    }
}

// ---------------- scoring kernel: warp per row ----------------
__global__ void __launch_bounds__(256)
score_kernel(float* __restrict__ out) {
    int lane = threadIdx.x & 31;
    int wid = blockIdx.x * (blockDim.x >> 5) + (threadIdx.x >> 5);
    int nw = gridDim.x * (blockDim.x >> 5);
    for (int row = wid; row < Bq; row += nw) {
        float v[12][8];
#pragma unroll
        for (int s = 0; s < 12; ++s) {
            const __half2* p = (const __half2*)g_z + ((size_t)s * Bq + row) * 128 + lane;
#pragma unroll
            for (int u = 0; u < 4; ++u) {
                float2 t = __half22float2(p[u * 32]);
                v[s][2 * u] = t.x; v[s][2 * u + 1] = t.y;
            }
        }
        float inrm[12];
#pragma unroll
        for (int s = 0; s < 12; ++s) {
            float d = 0.f;
#pragma unroll
            for (int u = 0; u < 8; ++u) d = fmaf(v[s][u], v[s][u], d);
#pragma unroll
            for (int o = 16; o; o >>= 1) d += __shfl_xor_sync(0xffffffffu, d, o);
            inrm[s] = sqrtf(d);
        }
        float negs[11];
#pragma unroll
        for (int k = 0; k < 11; ++k) negs[k] = 0.f;
#pragma unroll
        for (int l = 0; l < 11; ++l) {
#pragma unroll
            for (int k = l + 1; k < 11; ++k) {
                float d = 0.f;
#pragma unroll
                for (int u = 0; u < 8; ++u) d = fmaf(v[l][u], v[k][u], d);
#pragma unroll
                for (int o = 16; o; o >>= 1) d += __shfl_xor_sync(0xffffffffu, d, o);
                float e = expf(d / fmaxf(inrm[l] * inrm[k], 1e-8f));
                negs[l] += e; negs[k] += e;
            }
        }
        float tot = 0.f;
#pragma unroll
        for (int k = 0; k < 11; ++k) {
            float d = 0.f;
#pragma unroll
            for (int u = 0; u < 8; ++u) d = fmaf(v[11][u], v[k][u], d);
#pragma unroll
            for (int o = 16; o; o >>= 1) d += __shfl_xor_sync(0xffffffffu, d, o);
            float sim = expf(d / fmaxf(inrm[11] * inrm[k], 1e-8f));
            tot += log1pf(negs[k] / sim);
        }
        if (lane == 0) out[row] = tot;
    }
}

// ---------------- launcher ----------------
extern "C" void kernel_launch(void* const* d_in, const int* in_sizes, int n_in,
                              void* d_out, int out_size) {
    const float* x   = (const float*)d_in[0];
    const float* Tw1 = (const float*)d_in[1];
    const float* Tb1 = (const float*)d_in[2];
    const float* Tw2 = (const float*)d_in[3];
    const float* Tb2 = (const float*)d_in[4];
    const float* Ew1 = (const float*)d_in[5];
    const float* Eb1 = (const float*)d_in[6];
    const float* Ew2 = (const float*)d_in[7];
    const float* Eb2 = (const float*)d_in[8];
    float* out = (float*)d_out;

    cudaFuncSetAttribute(mlp_kernel, cudaFuncAttributeMaxDynamicSharedMemorySize, SM_BYTES);

    prep_kernel<<<192, 256>>>(Tw1, Tw2, Ew1, Ew2);
    mlp_kernel<<<Bq / 64, 256, SM_BYTES>>>(x, Tb1, Tb2, Eb1, Eb2);
    score_kernel<<<1024, 256>>>(out);
}

// round 15
// speedup vs baseline: 1.3696x; 1.0292x over previous
#include <cuda_runtime.h>
#include <cuda_fp16.h>
#include <math.h>
#include <stdint.h>

#define Bq 65536

// ---------------- device workspaces (sanctioned __device__ scratch) --------
__device__ __align__(16) unsigned char g_wb[24u * 131072u];     // 3 MB: BT fp16
__device__ __align__(16) unsigned short g_z[12ull * Bq * 256];  // z vectors fp16

// ---------------- SMEM layout (bytes) ----------------
// bias f32[256] @0 ; A @1024 (128 rows x 528 = 67584) ; B stages @68608 (2 x 16896)
#define BIAS_OFF 0
#define A_OFF 1024
#define BST_OFF 68608
#define SM_BYTES 102400
#define BPART 16896          // 32*528
#define ASTRIDE 528          // bytes per row (264 fp16)

// ---------------- helpers ----------------
__device__ __forceinline__ uint32_t smem_u32(const void* p) {
    uint32_t a;
    asm("{ .reg .u64 t; cvta.to.shared.u64 t, %1; cvt.u32.u64 %0, t; }" : "=r"(a) : "l"(p));
    return a;
}

#define LDSM4(r, addr) \
    asm volatile("ldmatrix.sync.aligned.m8n8.x4.shared.b16 {%0,%1,%2,%3}, [%4];" \
        : "=r"((r)[0]), "=r"((r)[1]), "=r"((r)[2]), "=r"((r)[3]) : "r"(addr))

#define MMA(acc, a, bb0, bb1) \
    asm volatile("mma.sync.aligned.m16n8k16.row.col.f32.f16.f16.f32 " \
        "{%0,%1,%2,%3},{%4,%5,%6,%7},{%8,%9},{%0,%1,%2,%3};" \
        : "+f"((acc)[0]), "+f"((acc)[1]), "+f"((acc)[2]), "+f"((acc)[3]) \
        : "r"((a)[0]), "r"((a)[1]), "r"((a)[2]), "r"((a)[3]), "r"(bb0), "r"(bb1))

__device__ __forceinline__ void cpa16(uint32_t dst, const void* src) {
    asm volatile("cp.async.cg.shared.global [%0], [%1], 16;" :: "r"(dst), "l"(src));
}
#define CP_COMMIT() asm volatile("cp.async.commit_group;" ::: "memory")
#define CP_WAIT0()  asm volatile("cp.async.wait_group 0;" ::: "memory")

__device__ __forceinline__ uint32_t pack_h2(float a, float b) {
    __half2 h = __floats2half2_rn(a, b);
    return *(uint32_t*)&h;
}

__device__ __forceinline__ float gelu_f(float v) {
    return 0.5f * v * (1.0f + erff(v * 0.70710678118654752f));
}

// ---------------- prep: weights -> BT fp16 blobs ----------------
__global__ void prep_kernel(const float* __restrict__ Tw1, const float* __restrict__ Tw2,
                            const float* __restrict__ Ew1, const float* __restrict__ Ew2) {
    int mat = blockIdx.x >> 3, sub = blockIdx.x & 7;
    const float* src = (mat < 11) ? Tw1 + (size_t)mat * 65536
                     : (mat < 22) ? Tw2 + (size_t)(mat - 11) * 65536
                     : (mat == 22) ? Ew1 : Ew2;
    unsigned char* baseH = g_wb + (size_t)mat * 131072u;
    for (int i = 0; i < 32; ++i) {
        int idx = sub * 8192 + i * 256 + threadIdx.x;
        int k = idx >> 8, n = idx & 255;
        __half h = __float2half_rn(src[idx]);
        *(unsigned short*)(baseH + (size_t)n * 512 + (size_t)k * 2) = *(unsigned short*)&h;
    }
}

// ---------------- main fused MLP kernel ----------------
extern __shared__ unsigned char smem[];

__device__ __forceinline__ void issueB(uint32_t sb, int tid, int mat, int c, int stage) {
    const unsigned char* srcbase = g_wb + (size_t)mat * 131072u;
    uint32_t dstbase = sb + BST_OFF + stage * BPART;
#pragma unroll
    for (int i = 0; i < 4; ++i) {
        int g = tid + 256 * i;           // 0..1023
        int rw = g >> 5;                 // row within chunk 0..31
        int u = g & 31;                  // 16B unit within 512B row
        uint32_t dst = dstbase + rw * ASTRIDE + u * 16;
        const unsigned char* s = srcbase + (size_t)(c * 32 + rw) * 512 + (size_t)u * 16;
        cpa16(dst, s);
    }
    CP_COMMIT();
}

__device__ __forceinline__ void do_layer(
    uint32_t sb, int tid, int mat, int nextMat,
    const float* __restrict__ biasPtr, bool do_gelu, bool toA,
    int slot, int b0)
{
    float* bias_s = (float*)(smem + BIAS_OFF);
    bias_s[tid] = biasPtr[tid];

    const int wm = tid >> 5, lane = tid & 31;   // warp owns rows wm*16..wm*16+15, all 32 cols
    const int gid = lane >> 2, tig = lane & 3;

    const int rowA = wm * 16 + (lane & 15);
    const int koffA = (lane >> 4) * 16;                      // bytes
    const int rowB = ((lane >> 4) << 3) + (lane & 7);        // 0..15
    const int koffB = ((lane >> 3) & 1) * 16;

    // ---- A-stationary: preload warp's A slice (16 rows x 256 k fp16 = 64 regs) ----
    const uint32_t aB = sb + A_OFF + rowA * ASTRIDE + koffA;
    uint32_t areg[16][4];
#pragma unroll
    for (int ks = 0; ks < 16; ++ks)
        LDSM4(areg[ks], aB + ks * 32);

#pragma unroll 1
    for (int c = 0; c < 8; ++c) {
        CP_WAIT0();
        __syncthreads();
        if (c + 1 < 8) issueB(sb, tid, mat, c + 1, (c + 1) & 1);
        else if (nextMat >= 0) issueB(sb, tid, nextMat, 0, 0);

        uint32_t bB = sb + BST_OFF + (c & 1) * BPART + rowB * ASTRIDE + koffB;

        float acc[4][4] = {};

#pragma unroll
        for (int ks = 0; ks < 16; ++ks) {
            uint32_t b0r[4], b1r[4];
            LDSM4(b0r, bB);
            LDSM4(b1r, bB + 16 * ASTRIDE);
            bB += 32;
            MMA(acc[0], areg[ks], b0r[0], b0r[1]);
            MMA(acc[1], areg[ks], b0r[2], b0r[3]);
            MMA(acc[2], areg[ks], b1r[0], b1r[1]);
            MMA(acc[3], areg[ks], b1r[2], b1r[3]);
        }

        // epilogue: warp owns 16 rows x 32 cols of this chunk
        const int r0 = wm * 16 + gid;
#pragma unroll
        for (int t = 0; t < 4; ++t) {
            const int gcol = c * 32 + t * 8 + 2 * tig;
            float v00 = acc[t][0] + bias_s[gcol];
            float v01 = acc[t][1] + bias_s[gcol + 1];
            float v10 = acc[t][2] + bias_s[gcol];
            float v11 = acc[t][3] + bias_s[gcol + 1];
            if (do_gelu) {
                v00 = gelu_f(v00); v01 = gelu_f(v01);
                v10 = gelu_f(v10); v11 = gelu_f(v11);
            }
            if (toA) {
                unsigned char* da = smem + A_OFF;
                *(uint32_t*)(da + r0 * ASTRIDE + gcol * 2)       = pack_h2(v00, v01);
                *(uint32_t*)(da + (r0 + 8) * ASTRIDE + gcol * 2) = pack_h2(v10, v11);
            } else {
                unsigned short* zb = g_z + ((size_t)slot * Bq + b0) * 256;
                *(uint32_t*)(zb + (size_t)r0 * 256 + gcol)       = pack_h2(v00, v01);
                *(uint32_t*)(zb + (size_t)(r0 + 8) * 256 + gcol) = pack_h2(v10, v11);
            }
        }
    }
    __syncthreads();
}

__global__ void __launch_bounds__(256, 2)
mlp_kernel(const float* __restrict__ x,
           const float* __restrict__ Tb1, const float* __restrict__ Tb2,
           const float* __restrict__ Eb1, const float* __restrict__ Eb2)
{
    const uint32_t sb = smem_u32(smem);
    const int tid = threadIdx.x;
    const int b0 = blockIdx.x * 128;

    issueB(sb, tid, 0, 0, 0);   // prefetch chunk0 of first layer

#pragma unroll 1
    for (int br = 0; br < 12; ++br) {
        // load x rows -> A (fp16): 128 rows, each thread does half a row
        {
            const int row = tid >> 1;
            const int cbase = (tid & 1) * 128;
            const float4* src = (const float4*)(x + (size_t)(b0 + row) * 256 + cbase);
            unsigned char* da = smem + A_OFF + row * ASTRIDE;
#pragma unroll
            for (int i = 0; i < 32; ++i) {
                float4 v = src[i];
                int col = cbase + i * 4;
                *(uint32_t*)(da + col * 2)     = pack_h2(v.x, v.y);
                *(uint32_t*)(da + col * 2 + 4) = pack_h2(v.z, v.w);
            }
        }
        __syncthreads();

        if (br < 11) {
            do_layer(sb, tid, br,      11 + br, Tb1 + br * 256, true,  true, 0, b0);
            do_layer(sb, tid, 11 + br, 22,      Tb2 + br * 256, false, true, 0, b0);
            do_layer(sb, tid, 22,      23,      Eb1, true,  true,  0,  b0);
            do_layer(sb, tid, 23, (br + 1 < 11) ? br + 1 : 22, Eb2, false, false, br, b0);
        } else {
            do_layer(sb, tid, 22, 23, Eb1, true,  true,  0,  b0);
            do_layer(sb, tid, 23, -1, Eb2, false, false, br, b0);
        }
    }
}

// ---------------- scoring kernel: warp per row ----------------
__global__ void __launch_bounds__(256)
score_kernel(float* __restrict__ out) {
    int lane = threadIdx.x & 31;
    int wid = blockIdx.x * (blockDim.x >> 5) + (threadIdx.x >> 5);
    int nw = gridDim.x * (blockDim.x >> 5);
    for (int row = wid; row < Bq; row += nw) {
        float v[12][8];
#pragma unroll
        for (int s = 0; s < 12; ++s) {
            const __half2* p = (const __half2*)g_z + ((size_t)s * Bq + row) * 128 + lane;
#pragma unroll
            for (int u = 0; u < 4; ++u) {
                float2 t = __half22float2(p[u * 32]);
                v[s][2 * u] = t.x; v[s][2 * u + 1] = t.y;
            }
        }
        float inrm[12];
#pragma unroll
        for (int s = 0; s < 12; ++s) {
            float d = 0.f;
#pragma unroll
            for (int u = 0; u < 8; ++u) d = fmaf(v[s][u], v[s][u], d);
#pragma unroll
            for (int o = 16; o; o >>= 1) d += __shfl_xor_sync(0xffffffffu, d, o);
            inrm[s] = sqrtf(d);
        }
        float negs[11];
#pragma unroll
        for (int k = 0; k < 11; ++k) negs[k] = 0.f;
#pragma unroll
        for (int l = 0; l < 11; ++l) {
#pragma unroll
            for (int k = l + 1; k < 11; ++k) {
                float d = 0.f;
#pragma unroll
                for (int u = 0; u < 8; ++u) d = fmaf(v[l][u], v[k][u], d);
#pragma unroll
                for (int o = 16; o; o >>= 1) d += __shfl_xor_sync(0xffffffffu, d, o);
                float e = expf(d / fmaxf(inrm[l] * inrm[k], 1e-8f));
                negs[l] += e; negs[k] += e;
            }
        }
        float tot = 0.f;
#pragma unroll
        for (int k = 0; k < 11; ++k) {
            float d = 0.f;
#pragma unroll
            for (int u = 0; u < 8; ++u) d = fmaf(v[11][u], v[k][u], d);
#pragma unroll
            for (int o = 16; o; o >>= 1) d += __shfl_xor_sync(0xffffffffu, d, o);
            float sim = expf(d / fmaxf(inrm[11] * inrm[k], 1e-8f));
            tot += log1pf(negs[k] / sim);
        }
        if (lane == 0) out[row] = tot;
    }
}

// ---------------- launcher ----------------
extern "C" void kernel_launch(void* const* d_in, const int* in_sizes, int n_in,
                              void* d_out, int out_size) {
    const float* x   = (const float*)d_in[0];
    const float* Tw1 = (const float*)d_in[1];
    const float* Tb1 = (const float*)d_in[2];
    const float* Tw2 = (const float*)d_in[3];
    const float* Tb2 = (const float*)d_in[4];
    const float* Ew1 = (const float*)d_in[5];
    const float* Eb1 = (const float*)d_in[6];
    const float* Ew2 = (const float*)d_in[7];
    const float* Eb2 = (const float*)d_in[8];
    float* out = (float*)d_out;

    cudaFuncSetAttribute(mlp_kernel, cudaFuncAttributeMaxDynamicSharedMemorySize, SM_BYTES);

    prep_kernel<<<192, 256>>>(Tw1, Tw2, Ew1, Ew2);
    mlp_kernel<<<Bq / 128, 256, SM_BYTES>>>(x, Tb1, Tb2, Eb1, Eb2);
    score_kernel<<<1024, 256>>>(out);
}

// round 16
// speedup vs baseline: 1.4050x; 1.0259x over previous
#include <cuda_runtime.h>
#include <cuda_fp16.h>
#include <math.h>
#include <stdint.h>

#define Bq 65536

// ---------------- device workspaces (sanctioned __device__ scratch) --------
__device__ __align__(16) unsigned char g_wb[24u * 131072u];     // 3 MB: BT fp16
__device__ __align__(16) unsigned short g_z[12ull * Bq * 256];  // z vectors fp16

// ---------------- SMEM layout (bytes) ----------------
// bias f32[256] @0 ; A @1024 (128 rows x 528 = 67584) ; B stages @68608 (2 x 16896)
#define BIAS_OFF 0
#define A_OFF 1024
#define BST_OFF 68608
#define SM_BYTES 102400
#define BPART 16896          // 32*528
#define ASTRIDE 528          // bytes per row (264 fp16)

// ---------------- helpers ----------------
__device__ __forceinline__ uint32_t smem_u32(const void* p) {
    uint32_t a;
    asm("{ .reg .u64 t; cvta.to.shared.u64 t, %1; cvt.u32.u64 %0, t; }" : "=r"(a) : "l"(p));
    return a;
}

#define LDSM4(r, addr) \
    asm volatile("ldmatrix.sync.aligned.m8n8.x4.shared.b16 {%0,%1,%2,%3}, [%4];" \
        : "=r"((r)[0]), "=r"((r)[1]), "=r"((r)[2]), "=r"((r)[3]) : "r"(addr))

#define MMA(acc, a, bb0, bb1) \
    asm volatile("mma.sync.aligned.m16n8k16.row.col.f32.f16.f16.f32 " \
        "{%0,%1,%2,%3},{%4,%5,%6,%7},{%8,%9},{%0,%1,%2,%3};" \
        : "+f"((acc)[0]), "+f"((acc)[1]), "+f"((acc)[2]), "+f"((acc)[3]) \
        : "r"((a)[0]), "r"((a)[1]), "r"((a)[2]), "r"((a)[3]), "r"(bb0), "r"(bb1))

__device__ __forceinline__ void cpa16(uint32_t dst, const void* src) {
    asm volatile("cp.async.cg.shared.global [%0], [%1], 16;" :: "r"(dst), "l"(src));
}
#define CP_COMMIT() asm volatile("cp.async.commit_group;" ::: "memory")
#define CP_WAIT0()  asm volatile("cp.async.wait_group 0;" ::: "memory")

__device__ __forceinline__ uint32_t pack_h2(float a, float b) {
    __half2 h = __floats2half2_rn(a, b);
    return *(uint32_t*)&h;
}

__device__ __forceinline__ float gelu_f(float v) {
    return 0.5f * v * (1.0f + erff(v * 0.70710678118654752f));
}

// ---------------- prep: weights -> BT fp16 blobs ----------------
__global__ void prep_kernel(const float* __restrict__ Tw1, const float* __restrict__ Tw2,
                            const float* __restrict__ Ew1, const float* __restrict__ Ew2) {
    int mat = blockIdx.x >> 3, sub = blockIdx.x & 7;
    const float* src = (mat < 11) ? Tw1 + (size_t)mat * 65536
                     : (mat < 22) ? Tw2 + (size_t)(mat - 11) * 65536
                     : (mat == 22) ? Ew1 : Ew2;
    unsigned char* baseH = g_wb + (size_t)mat * 131072u;
    for (int i = 0; i < 32; ++i) {
        int idx = sub * 8192 + i * 256 + threadIdx.x;
        int k = idx >> 8, n = idx & 255;
        __half h = __float2half_rn(src[idx]);
        *(unsigned short*)(baseH + (size_t)n * 512 + (size_t)k * 2) = *(unsigned short*)&h;
    }
}

// ---------------- main fused MLP kernel ----------------
extern __shared__ unsigned char smem[];

__device__ __forceinline__ void issueB(uint32_t sb, int tid, int mat, int c, int stage) {
    const unsigned char* srcbase = g_wb + (size_t)mat * 131072u;
    uint32_t dstbase = sb + BST_OFF + stage * BPART;
#pragma unroll
    for (int i = 0; i < 4; ++i) {
        int g = tid + 256 * i;           // 0..1023
        int rw = g >> 5;                 // row within chunk 0..31
        int u = g & 31;                  // 16B unit within 512B row
        uint32_t dst = dstbase + rw * ASTRIDE + u * 16;
        const unsigned char* s = srcbase + (size_t)(c * 32 + rw) * 512 + (size_t)u * 16;
        cpa16(dst, s);
    }
    CP_COMMIT();
}

__device__ __forceinline__ void do_layer(
    uint32_t sb, int tid, int mat, int nextMat,
    const float* __restrict__ biasPtr, bool do_gelu, bool toA,
    int slot, int b0)
{
    float* bias_s = (float*)(smem + BIAS_OFF);
    bias_s[tid] = biasPtr[tid];

    const int wm = tid >> 5, lane = tid & 31;   // warp owns rows wm*16..wm*16+15, all 32 cols
    const int gid = lane >> 2, tig = lane & 3;

    const int rowA = wm * 16 + (lane & 15);
    const int koffA = (lane >> 4) * 16;                      // bytes
    const int rowB = ((lane >> 4) << 3) + (lane & 7);        // 0..15
    const int koffB = ((lane >> 3) & 1) * 16;

    // ---- A-stationary: preload warp's A slice (16 rows x 256 k fp16 = 64 regs) ----
    const uint32_t aB = sb + A_OFF + rowA * ASTRIDE + koffA;
    uint32_t areg[16][4];
#pragma unroll
    for (int ks = 0; ks < 16; ++ks)
        LDSM4(areg[ks], aB + ks * 32);

#pragma unroll 1
    for (int c = 0; c < 8; ++c) {
        CP_WAIT0();
        __syncthreads();
        if (c + 1 < 8) issueB(sb, tid, mat, c + 1, (c + 1) & 1);
        else if (nextMat >= 0) issueB(sb, tid, nextMat, 0, 0);

        uint32_t bB = sb + BST_OFF + (c & 1) * BPART + rowB * ASTRIDE + koffB;

        float acc[4][4] = {};

#pragma unroll
        for (int ks = 0; ks < 16; ++ks) {
            uint32_t b0r[4], b1r[4];
            LDSM4(b0r, bB);
            LDSM4(b1r, bB + 16 * ASTRIDE);
            bB += 32;
            MMA(acc[0], areg[ks], b0r[0], b0r[1]);
            MMA(acc[1], areg[ks], b0r[2], b0r[3]);
            MMA(acc[2], areg[ks], b1r[0], b1r[1]);
            MMA(acc[3], areg[ks], b1r[2], b1r[3]);
        }

        // epilogue: warp owns 16 rows x 32 cols of this chunk
        const int r0 = wm * 16 + gid;
#pragma unroll
        for (int t = 0; t < 4; ++t) {
            const int gcol = c * 32 + t * 8 + 2 * tig;
            float v00 = acc[t][0] + bias_s[gcol];
            float v01 = acc[t][1] + bias_s[gcol + 1];
            float v10 = acc[t][2] + bias_s[gcol];
            float v11 = acc[t][3] + bias_s[gcol + 1];
            if (do_gelu) {
                v00 = gelu_f(v00); v01 = gelu_f(v01);
                v10 = gelu_f(v10); v11 = gelu_f(v11);
            }
            if (toA) {
                unsigned char* da = smem + A_OFF;
                *(uint32_t*)(da + r0 * ASTRIDE + gcol * 2)       = pack_h2(v00, v01);
                *(uint32_t*)(da + (r0 + 8) * ASTRIDE + gcol * 2) = pack_h2(v10, v11);
            } else {
                unsigned short* zb = g_z + ((size_t)slot * Bq + b0) * 256;
                *(uint32_t*)(zb + (size_t)r0 * 256 + gcol)       = pack_h2(v00, v01);
                *(uint32_t*)(zb + (size_t)(r0 + 8) * 256 + gcol) = pack_h2(v10, v11);
            }
        }
    }
    __syncthreads();
}

// one CTA = one (tile, branch) job;  grid = (B/128) * 12
__global__ void __launch_bounds__(256, 2)
mlp_kernel(const float* __restrict__ x,
           const float* __restrict__ Tb1, const float* __restrict__ Tb2,
           const float* __restrict__ Eb1, const float* __restrict__ Eb2)
{
    const uint32_t sb = smem_u32(smem);
    const int tid = threadIdx.x;
    const int br = blockIdx.x % 12;
    const int b0 = (blockIdx.x / 12) * 128;

    const int mat0 = (br < 11) ? br : 22;
    issueB(sb, tid, mat0, 0, 0);   // prefetch chunk0 of first layer

    // load x rows -> A (fp16): 128 rows, each thread does half a row
    {
        const int row = tid >> 1;
        const int cbase = (tid & 1) * 128;
        const float4* src = (const float4*)(x + (size_t)(b0 + row) * 256 + cbase);
        unsigned char* da = smem + A_OFF + row * ASTRIDE;
#pragma unroll
        for (int i = 0; i < 32; ++i) {
            float4 v = src[i];
            int col = cbase + i * 4;
            *(uint32_t*)(da + col * 2)     = pack_h2(v.x, v.y);
            *(uint32_t*)(da + col * 2 + 4) = pack_h2(v.z, v.w);
        }
    }
    __syncthreads();

    if (br < 11) {
        do_layer(sb, tid, br,      11 + br, Tb1 + br * 256, true,  true,  0,  b0);
        do_layer(sb, tid, 11 + br, 22,      Tb2 + br * 256, false, true,  0,  b0);
        do_layer(sb, tid, 22,      23,      Eb1, true,  true,  0,  b0);
        do_layer(sb, tid, 23,      -1,      Eb2, false, false, br, b0);
    } else {
        do_layer(sb, tid, 22, 23, Eb1, true,  true,  0,  b0);
        do_layer(sb, tid, 23, -1, Eb2, false, false, br, b0);
    }
}

// ---------------- scoring kernel: warp per row ----------------
__global__ void __launch_bounds__(256)
score_kernel(float* __restrict__ out) {
    int lane = threadIdx.x & 31;
    int wid = blockIdx.x * (blockDim.x >> 5) + (threadIdx.x >> 5);
    int nw = gridDim.x * (blockDim.x >> 5);
    for (int row = wid; row < Bq; row += nw) {
        float v[12][8];
#pragma unroll
        for (int s = 0; s < 12; ++s) {
            const __half2* p = (const __half2*)g_z + ((size_t)s * Bq + row) * 128 + lane;
#pragma unroll
            for (int u = 0; u < 4; ++u) {
                float2 t = __half22float2(p[u * 32]);
                v[s][2 * u] = t.x; v[s][2 * u + 1] = t.y;
            }
        }
        float inrm[12];
#pragma unroll
        for (int s = 0; s < 12; ++s) {
            float d = 0.f;
#pragma unroll
            for (int u = 0; u < 8; ++u) d = fmaf(v[s][u], v[s][u], d);
#pragma unroll
            for (int o = 16; o; o >>= 1) d += __shfl_xor_sync(0xffffffffu, d, o);
            inrm[s] = sqrtf(d);
        }
        float negs[11];
#pragma unroll
        for (int k = 0; k < 11; ++k) negs[k] = 0.f;
#pragma unroll
        for (int l = 0; l < 11; ++l) {
#pragma unroll
            for (int k = l + 1; k < 11; ++k) {
                float d = 0.f;
#pragma unroll
                for (int u = 0; u < 8; ++u) d = fmaf(v[l][u], v[k][u], d);
#pragma unroll
                for (int o = 16; o; o >>= 1) d += __shfl_xor_sync(0xffffffffu, d, o);
                float e = expf(d / fmaxf(inrm[l] * inrm[k], 1e-8f));
                negs[l] += e; negs[k] += e;
            }
        }
        float tot = 0.f;
#pragma unroll
        for (int k = 0; k < 11; ++k) {
            float d = 0.f;
#pragma unroll
            for (int u = 0; u < 8; ++u) d = fmaf(v[11][u], v[k][u], d);
#pragma unroll
            for (int o = 16; o; o >>= 1) d += __shfl_xor_sync(0xffffffffu, d, o);
            float sim = expf(d / fmaxf(inrm[11] * inrm[k], 1e-8f));
            tot += log1pf(negs[k] / sim);
        }
        if (lane == 0) out[row] = tot;
    }
}

// ---------------- launcher ----------------
extern "C" void kernel_launch(void* const* d_in, const int* in_sizes, int n_in,
                              void* d_out, int out_size) {
    const float* x   = (const float*)d_in[0];
    const float* Tw1 = (const float*)d_in[1];
    const float* Tb1 = (const float*)d_in[2];
    const float* Tw2 = (const float*)d_in[3];
    const float* Tb2 = (const float*)d_in[4];
    const float* Ew1 = (const float*)d_in[5];
    const float* Eb1 = (const float*)d_in[6];
    const float* Ew2 = (const float*)d_in[7];
    const float* Eb2 = (const float*)d_in[8];
    float* out = (float*)d_out;

    cudaFuncSetAttribute(mlp_kernel, cudaFuncAttributeMaxDynamicSharedMemorySize, SM_BYTES);

    prep_kernel<<<192, 256>>>(Tw1, Tw2, Ew1, Ew2);
    mlp_kernel<<<(Bq / 128) * 12, 256, SM_BYTES>>>(x, Tb1, Tb2, Eb1, Eb2);
    score_kernel<<<1024, 256>>>(out);
}